// round 1
// baseline (speedup 1.0000x reference)
#include <cuda_runtime.h>
#include <cuda_bf16.h>

// out[s,b,d] = x[s,b,0]*W_xy[d,0] + x[s,b,1]*W_xy[d,1]
//            + x[s,b,2]*W_seg[d] + b_xy[d] + b_seg[d] + pe[s,d]
//
// S=256, B=256, D=1024. Output 268 MB fp32 -> store-bandwidth bound.
// Strategy: fixed-d threads keep all per-d coefficients in registers,
// loop over b; steady-state memory traffic = stores only.

#define S_DIM 256
#define B_DIM 256
#define D_DIM 1024
#define B_PER_BLK 32           // b values per block
#define CHUNKS (B_DIM / B_PER_BLK)   // 8 chunks per s

__global__ __launch_bounds__(256, 8)
void pe_fused_kernel(const float* __restrict__ x,
                     const float* __restrict__ Wxy,
                     const float* __restrict__ bxy,
                     const float* __restrict__ Wseg,
                     const float* __restrict__ bseg,
                     const float* __restrict__ pe,
                     float* __restrict__ out)
{
    __shared__ float xs[B_PER_BLK * 3];

    const int s  = blockIdx.x >> 3;          // / CHUNKS
    const int b0 = (blockIdx.x & (CHUNKS - 1)) * B_PER_BLK;
    const int d  = threadIdx.x << 2;         // float4 per thread covers D=1024

    // Stage x[s, b0 : b0+32, 0:3] (96 contiguous floats) into shared.
    if (threadIdx.x < B_PER_BLK * 3)
        xs[threadIdx.x] = x[(size_t)(s * B_DIM + b0) * 3 + threadIdx.x];

    // Per-d coefficients -> registers (block-lifetime, loaded once).
    // W_xy is [D,2] row-major: rows d..d+3 are 8 interleaved floats.
    const float4 w01 = *reinterpret_cast<const float4*>(Wxy + d * 2);
    const float4 w23 = *reinterpret_cast<const float4*>(Wxy + d * 2 + 4);
    const float4 c2  = *reinterpret_cast<const float4*>(Wseg + d);
    const float4 ba  = *reinterpret_cast<const float4*>(bxy + d);
    const float4 bs  = *reinterpret_cast<const float4*>(bseg + d);
    const float4 p   = *reinterpret_cast<const float4*>(pe + (size_t)s * D_DIM + d);

    const float c0x = w01.x, c1x = w01.y;   // d+0
    const float c0y = w01.z, c1y = w01.w;   // d+1
    const float c0z = w23.x, c1z = w23.y;   // d+2
    const float c0w = w23.z, c1w = w23.w;   // d+3

    float4 base;
    base.x = p.x + ba.x + bs.x;
    base.y = p.y + ba.y + bs.y;
    base.z = p.z + ba.z + bs.z;
    base.w = p.w + ba.w + bs.w;

    __syncthreads();

    float4* o = reinterpret_cast<float4*>(
        out + (size_t)(s * B_DIM + b0) * D_DIM + d);

    #pragma unroll 8
    for (int i = 0; i < B_PER_BLK; ++i) {
        const float x0 = xs[i * 3 + 0];
        const float x1 = xs[i * 3 + 1];
        const float x2 = xs[i * 3 + 2];
        float4 r;
        r.x = fmaf(x0, c0x, fmaf(x1, c1x, fmaf(x2, c2.x, base.x)));
        r.y = fmaf(x0, c0y, fmaf(x1, c1y, fmaf(x2, c2.y, base.y)));
        r.z = fmaf(x0, c0z, fmaf(x1, c1z, fmaf(x2, c2.z, base.z)));
        r.w = fmaf(x0, c0w, fmaf(x1, c1w, fmaf(x2, c2.w, base.w)));
        o[i * (D_DIM / 4)] = r;
    }
}

extern "C" void kernel_launch(void* const* d_in, const int* in_sizes, int n_in,
                              void* d_out, int out_size)
{
    const float* x    = (const float*)d_in[0];   // [S,B,3]
    const float* Wxy  = (const float*)d_in[1];   // [D,2]
    const float* bxy  = (const float*)d_in[2];   // [D]
    const float* Wseg = (const float*)d_in[3];   // [D,1]
    const float* bseg = (const float*)d_in[4];   // [D]
    const float* pe   = (const float*)d_in[5];   // [MAX_LEN,1,D]
    float* out = (float*)d_out;                  // [S,B,D]

    pe_fused_kernel<<<S_DIM * CHUNKS, 256>>>(x, Wxy, bxy, Wseg, bseg, pe, out);
}